// round 16
// baseline (speedup 1.0000x reference)
#include <cuda_runtime.h>
#include <cuda_bf16.h>
#include <cuda_fp16.h>
#include <math.h>
#include <stdint.h>

#define B_ 4
#define C_ 256
#define N_ 4096
#define D_ 32
#define LOG2E 1.4426950408889634f

// ---------------------------------------------------------------------------
// PTX helpers (base sm_100-safe)
// ---------------------------------------------------------------------------
__device__ __forceinline__ uint32_t smem_u32(const void* p) {
    uint32_t a;
    asm("{ .reg .u64 t; cvta.to.shared.u64 t, %1; cvt.u32.u64 %0, t; }" : "=r"(a) : "l"(p));
    return a;
}
#define MBARRIER_INIT(a, c) \
    asm volatile("mbarrier.init.shared.b64 [%0], %1;" :: "r"((uint32_t)(a)), "r"((uint32_t)(c)) : "memory")
#define MBARRIER_EXPECT_TX(a, n) \
    asm volatile("mbarrier.arrive.expect_tx.shared.b64 _, [%0], %1;" :: "r"((uint32_t)(a)), "r"((uint32_t)(n)) : "memory")
#define MBARRIER_WAIT_PARITY(a, ph) do { \
    uint32_t _m = (uint32_t)(a); uint32_t _p = (uint32_t)(ph); uint32_t _d; \
    asm volatile("{\n\t.reg .pred p;\n\tmbarrier.try_wait.parity.shared.b64 p, [%1], %2;\n\tselp.b32 %0,1,0,p;\n\t}" \
        : "=r"(_d) : "r"(_m), "r"(_p) : "memory"); \
    if (!_d) { \
        asm volatile("{\n\t.reg .pred P1;\n\tWL_%=:\n\tmbarrier.try_wait.parity.shared.b64 P1, [%0], %1;\n\t@P1 bra.uni WD_%=;\n\tbra.uni WL_%=;\n\tWD_%=:\n\t}" \
            :: "r"(_m), "r"(_p) : "memory"); \
    } } while (0)

__device__ __forceinline__ void cpasync16(uint32_t dst, const void* src) {
    asm volatile("cp.async.cg.shared.global [%0], [%1], 16;" :: "r"(dst), "l"(src) : "memory");
}
#define CP_COMMIT() asm volatile("cp.async.commit_group;" ::: "memory")
#define CP_WAIT(n)  asm volatile("cp.async.wait_group %0;" :: "n"(n) : "memory")

__device__ __forceinline__ void bulkcp(uint32_t dst, const void* src, uint32_t bytes, uint32_t mbar) {
    asm volatile("cp.async.bulk.shared::cta.global.mbarrier::complete_tx::bytes [%0], [%1], %2, [%3];"
                 :: "r"(dst), "l"(src), "r"(bytes), "r"(mbar) : "memory");
}

__device__ __forceinline__ void mma_bf(float* d, const uint32_t* a, const uint32_t* b) {
    asm volatile("mma.sync.aligned.m16n8k16.row.col.f32.bf16.bf16.f32 "
                 "{%0,%1,%2,%3}, {%4,%5,%6,%7}, {%8,%9}, {%0,%1,%2,%3};"
                 : "+f"(d[0]), "+f"(d[1]), "+f"(d[2]), "+f"(d[3])
                 : "r"(a[0]), "r"(a[1]), "r"(a[2]), "r"(a[3]), "r"(b[0]), "r"(b[1]));
}
__device__ __forceinline__ void mma_fp(float* d, const uint32_t* a, const uint32_t* b) {
    asm volatile("mma.sync.aligned.m16n8k16.row.col.f32.f16.f16.f32 "
                 "{%0,%1,%2,%3}, {%4,%5,%6,%7}, {%8,%9}, {%0,%1,%2,%3};"
                 : "+f"(d[0]), "+f"(d[1]), "+f"(d[2]), "+f"(d[3])
                 : "r"(a[0]), "r"(a[1]), "r"(a[2]), "r"(a[3]), "r"(b[0]), "r"(b[1]));
}
__device__ __forceinline__ void ldsm4(uint32_t* r, uint32_t addr) {
    asm volatile("ldmatrix.sync.aligned.m8n8.x4.shared.b16 {%0,%1,%2,%3}, [%4];"
                 : "=r"(r[0]), "=r"(r[1]), "=r"(r[2]), "=r"(r[3]) : "r"(addr));
}
__device__ __forceinline__ uint32_t pack_bf16x2(float x, float y) {
    __nv_bfloat162 h = __floats2bfloat162_rn(x, y);
    return *(uint32_t*)&h;
}
__device__ __forceinline__ uint32_t pack_h2(float x, float y) {
    __half2 h = __floats2half2_rn(x, y);
    return *(uint32_t*)&h;
}

#define RS 144
__device__ __forceinline__ int aoffA(int lane) { return (lane & 15) * RS + (lane >> 4) * 16; }
__device__ __forceinline__ int aoffB(int lane) { return ((lane & 7) + ((lane >> 4) << 3)) * RS + (lane & 8) * 2; }
__device__ __forceinline__ uint32_t swz64(int row, int chunk) {
    return (uint32_t)(row * 64 + ((chunk ^ ((row >> 1) & 3)) << 4));
}

// ---------------------------------------------------------------------------
// Scratch
// ---------------------------------------------------------------------------
__device__ char   g_qt [B_*64*64*64];
__device__ char   g_kt [B_*64*64*64];
__device__ char   g_vt [(size_t)B_*64*256*128];
__device__ __half g_ao [B_*N_*C_];
__device__ __half g_xt [B_*N_*C_];
__device__ __half g_wohi[C_*C_];
__device__ __half g_wolo[C_*C_];
__device__ __half g_wv [C_*C_];
__device__ __half g_wq [D_*C_];
__device__ __half g_wk [D_*C_];

// ---------------------------------------------------------------------------
__global__ void wprep_all_kernel(const float* __restrict__ wo, const float* __restrict__ wv,
                                 const float* __restrict__ wq, const float* __restrict__ wk,
                                 __half* __restrict__ woh, __half* __restrict__ wol,
                                 __half* __restrict__ wvp, __half* __restrict__ wqp,
                                 __half* __restrict__ wkp)
{
    int which = blockIdx.y;
    int i = blockIdx.x * 256 + threadIdx.x;
    if (which == 0) {
        float f = wo[i];
        __half h = __float2half_rn(f);
        woh[i] = h;
        wol[i] = __float2half_rn(f - __half2float(h));
    } else if (which == 1) {
        wvp[i] = __float2half_rn(wv[i]);
    } else if (which == 2) {
        if (i < D_ * C_) wqp[i] = __float2half_rn(wq[i] * LOG2E);
    } else {
        if (i < D_ * C_) wkp[i] = __float2half_rn(wk[i]);
    }
}

// ---------------------------------------------------------------------------
__global__ __launch_bounds__(256)
void xt_pack_kernel(const float* __restrict__ x, __half* __restrict__ xt)
{
    __shared__ float ts[64][65];
    const int b = blockIdx.z, c0 = blockIdx.y * 64, n0 = blockIdx.x * 64;
    const int t = threadIdx.x;
    const int rr = t >> 4, c4 = t & 15;

#pragma unroll
    for (int it = 0; it < 4; it++) {
        int row = it * 16 + rr;
        float4 v = *(const float4*)&x[(size_t)(b * C_ + c0 + row) * N_ + n0 + c4 * 4];
        ts[row][c4 * 4 + 0] = v.x; ts[row][c4 * 4 + 1] = v.y;
        ts[row][c4 * 4 + 2] = v.z; ts[row][c4 * 4 + 3] = v.w;
    }
    __syncthreads();
#pragma unroll
    for (int it = 0; it < 4; it++) {
        int n = it * 16 + rr;
        unsigned short hs[4];
#pragma unroll
        for (int e = 0; e < 4; e++)
            hs[e] = __half_as_ushort(__float2half_rn(ts[c4 * 4 + e][n]));
        *(uint2*)&xt[(size_t)(b * N_ + n0 + n) * C_ + c0 + c4 * 4] = *(uint2*)hs;
    }
}

// ---------------------------------------------------------------------------
// Q+K projection GEMM (fp16) -> 64B-row swizzled g_qt, g_kt
// ---------------------------------------------------------------------------
#define QK_XT 0
#define QK_WB 73728
#define QK_SMEM 110592

__global__ __launch_bounds__(256, 1)
void qk_mma_kernel(const __half* __restrict__ xt,
                   const __half* __restrict__ wqp, const __half* __restrict__ wkp,
                   const float* __restrict__ bq, const float* __restrict__ bk,
                   char* __restrict__ qt, char* __restrict__ kt)
{
    extern __shared__ char sm[];
    const uint32_t sb = smem_u32(sm);
    const int t = threadIdx.x;
    const int wid = t >> 5, lane = t & 31;
    const int g = lane >> 2, tg = lane & 3;
    const int oA = aoffA(lane), oB = aoffB(lane);
    const int wm = wid >> 1, wn = wid & 1;
    const int b = blockIdx.y, n0 = blockIdx.x * 128;

#pragma unroll
    for (int it = 0; it < 16; it++) {
        int idx = t + it * 256;
        int r = idx >> 5, cc = idx & 31;
        uint32_t off = (cc >> 3) * 18432 + r * RS + (cc & 7) * 16;
        cpasync16(sb + QK_XT + off, xt + (size_t)(b * N_ + n0 + r) * C_ + cc * 8);
    }
#pragma unroll
    for (int it = 0; it < 8; it++) {
        int idx = t + it * 256;
        int o = idx >> 5, cc = idx & 31;
        uint32_t off = (cc >> 3) * 9216 + o * RS + (cc & 7) * 16;
        const __half* sh = (o < 32) ? (wqp + (size_t)o * C_) : (wkp + (size_t)(o - 32) * C_);
        cpasync16(sb + QK_WB + off, sh + cc * 8);
    }
    CP_COMMIT();
    CP_WAIT(0);
    __syncthreads();

    float oac[2][4][4];
#pragma unroll
    for (int i = 0; i < 2; i++)
#pragma unroll
        for (int j = 0; j < 4; j++)
#pragma unroll
            for (int c = 0; c < 4; c++) oac[i][j][c] = 0.f;

#pragma unroll
    for (int kc = 0; kc < 4; kc++) {
#pragma unroll
        for (int ks = 0; ks < 4; ks++) {
            uint32_t ah[2][4];
#pragma unroll
            for (int mf = 0; mf < 2; mf++)
                ldsm4(ah[mf], sb + QK_XT + kc * 18432 + (wm * 32 + mf * 16) * RS + ks * 32 + oA);
#pragma unroll
            for (int j = 0; j < 2; j++) {
                uint32_t bh[4];
                ldsm4(bh, sb + QK_WB + kc * 9216 + (wn * 32 + j * 16) * RS + ks * 32 + oB);
#pragma unroll
                for (int h = 0; h < 2; h++)
#pragma unroll
                    for (int mf = 0; mf < 2; mf++)
                        mma_fp(oac[mf][j * 2 + h], ah[mf], &bh[2 * h]);
            }
        }
    }

#pragma unroll
    for (int mf = 0; mf < 2; mf++) {
#pragma unroll
        for (int half = 0; half < 2; half++) {
            const int rA = wm * 32 + mf * 16 + half * 8 + g;
            const int n = n0 + rA;
            const int tile = n >> 6, rr = n & 63;
#pragma unroll
            for (int hh = 0; hh < 4; hh++) {
                int o = wn * 32 + hh * 8 + 2 * tg;
                bool isq = (o < 32);
                int oo = isq ? o : (o - 32);
                float bb0 = isq ? bq[oo] * LOG2E : bk[oo];
                float bb1 = isq ? bq[oo + 1] * LOG2E : bk[oo + 1];
                float d0 = oac[mf][hh][half * 2 + 0] + bb0;
                float d1 = oac[mf][hh][half * 2 + 1] + bb1;
                char* dst = (isq ? qt : kt) + ((size_t)(b * 64 + tile) * 64) * 64;
                *(uint32_t*)(dst + swz64(rr, oo >> 3) + ((oo * 2) & 15)) = pack_h2(d0, d1);
            }
        }
    }
}

// ---------------------------------------------------------------------------
// V projection GEMM (fp16) -> swizzled bf16 g_vt.  3-stage cp.async pipeline.
// ---------------------------------------------------------------------------
#define VP_W 0
#define VP_X 18432
#define VP_BUF 36864
#define VP_SMEM 110592

__global__ __launch_bounds__(512, 1)
void v_mma_kernel(const __half* __restrict__ xt, const __half* __restrict__ wvp,
                  const float* __restrict__ bv, char* __restrict__ vt)
{
    extern __shared__ char sm[];
    const uint32_t sb = smem_u32(sm);
    const int t = threadIdx.x;
    const int wid = t >> 5, lane = t & 31;
    const int g = lane >> 2, tg = lane & 3;
    const int oA = aoffA(lane), oB = aoffB(lane);
    const int wm = wid >> 2, wn = wid & 3;
    const int b = blockIdx.z, o0 = blockIdx.y * 128, m0 = blockIdx.x * 128;

    float oac[2][4][4];
#pragma unroll
    for (int i = 0; i < 2; i++)
#pragma unroll
        for (int j = 0; j < 4; j++)
#pragma unroll
            for (int c = 0; c < 4; c++) oac[i][j][c] = 0.f;

    auto load_stage = [&](int kt_, int buf) {
        const uint32_t base = sb + buf * VP_BUF;
#pragma unroll
        for (int it = 0; it < 4; it++) {
            int idx = t + it * 512;
            int arr = idx >> 10, rr = (idx >> 3) & 127, cc = idx & 7;
            uint32_t dst = base + arr * 18432 + rr * RS + cc * 16;
            const __half* src = arr ? (xt + (size_t)(b * N_ + m0 + rr) * C_ + kt_ + cc * 8)
                                    : (wvp + (size_t)(o0 + rr) * C_ + kt_ + cc * 8);
            cpasync16(dst, src);
        }
        CP_COMMIT();
    };

    load_stage(0, 0);
    load_stage(64, 1);
    for (int s = 0; s < 4; s++) {
        if (s + 2 < 4) { load_stage((s + 2) * 64, (s + 2) % 3); CP_WAIT(2); }
        else if (s + 1 < 4) CP_WAIT(1);
        else CP_WAIT(0);
        __syncthreads();
        const uint32_t base = sb + (s % 3) * VP_BUF;
        const uint32_t Wp = base + VP_W + (wm * 32) * RS + oA;
        const uint32_t Xp = base + VP_X + (wn * 32) * RS + oB;
#pragma unroll
        for (int ks = 0; ks < 4; ks++) {
            uint32_t aw[2][4];
#pragma unroll
            for (int mf = 0; mf < 2; mf++)
                ldsm4(aw[mf], Wp + mf * 16 * RS + ks * 32);
#pragma unroll
            for (int j = 0; j < 2; j++) {
                uint32_t bh[4];
                ldsm4(bh, Xp + j * 16 * RS + ks * 32);
#pragma unroll
                for (int h = 0; h < 2; h++)
#pragma unroll
                    for (int mf = 0; mf < 2; mf++)
                        mma_fp(oac[mf][j * 2 + h], aw[mf], &bh[2 * h]);
            }
        }
        __syncthreads();
    }

#pragma unroll
    for (int mf = 0; mf < 2; mf++) {
#pragma unroll
        for (int half = 0; half < 2; half++) {
            const int rA = o0 + wm * 32 + mf * 16 + half * 8 + g;
            const float bvA = bv[rA];
            const int swx = (rA & 7) << 4;
#pragma unroll
            for (int nf = 0; nf < 4; nf++) {
                const int m = m0 + wn * 32 + nf * 8 + 2 * tg;
                const int tile = m >> 6, j = m & 63;
                char* dst = vt + ((size_t)(b * 64 + tile) * 256 + rA) * 128;
                *(uint32_t*)(dst + ((j * 2) ^ swx)) =
                    pack_bf16x2(oac[mf][nf][half * 2 + 0] + bvA, oac[mf][nf][half * 2 + 1] + bvA);
            }
        }
    }
}

// ---------------------------------------------------------------------------
// Flash attention, register-resident P (unchanged from R15).
// ---------------------------------------------------------------------------
#define OFF_LSUM 64
#define OFF_Q2   1024
#define OFF_K0   9216
#define OFF_K1   13312
#define OFF_V0   17408
#define ATTN_SMEM 115712

__global__ __launch_bounds__(256, 1)
void attn_mma_kernel(const char* __restrict__ qt,
                     const char* __restrict__ kt,
                     const char* __restrict__ vt,
                     __half* __restrict__ ao)
{
    extern __shared__ char sm[];
    const uint32_t sb = smem_u32(sm);
    const int t = threadIdx.x;
    const int wid = t >> 5, lane = t & 31;
    const int g = lane >> 2, tg = lane & 3;
    const int b = blockIdx.y, m0 = blockIdx.x * 128;

    const int arow = lane & 15, achk = lane >> 4;
    const int brow = (lane & 7) + ((lane >> 4) << 3), bchk = (lane >> 3) & 1;
    const int vrow = (lane & 7) + ((lane >> 4) << 3), vcol = (lane & 8) * 2, vx = (lane & 7) << 4;

    const char* qt_b = qt + ((size_t)(b * 64 + (m0 >> 6))) * 4096;
    const char* kt_b = kt + (size_t)b * 64 * 4096;
    const char* vt_b = vt + (size_t)b * 64 * 32768;

    float* lsum_s = (float*)(sm + OFF_LSUM);
    if (t == 0) {
        MBARRIER_INIT(sb + 0, 1);  MBARRIER_INIT(sb + 8, 1);
        MBARRIER_INIT(sb + 16, 1); MBARRIER_INIT(sb + 24, 1); MBARRIER_INIT(sb + 32, 1);
    }
    if (t < 128) lsum_s[t] = 0.f;

#pragma unroll
    for (int i = 0; i < 2; i++) {
        int idx = t + i * 256;
        cpasync16(sb + OFF_Q2 + idx * 16, qt_b + idx * 16);
    }
    CP_COMMIT();
    __syncthreads();

    if (t == 0) {
        MBARRIER_EXPECT_TX(sb + 0, 4096);  bulkcp(sb + OFF_K0, kt_b, 4096, sb + 0);
        MBARRIER_EXPECT_TX(sb + 8, 4096);  bulkcp(sb + OFF_K1, kt_b + 4096, 4096, sb + 8);
        MBARRIER_EXPECT_TX(sb + 16, 32768); bulkcp(sb + OFF_V0, vt_b, 32768, sb + 16);
        MBARRIER_EXPECT_TX(sb + 24, 32768); bulkcp(sb + OFF_V0 + 32768, vt_b + 32768, 32768, sb + 24);
        MBARRIER_EXPECT_TX(sb + 32, 32768); bulkcp(sb + OFF_V0 + 65536, vt_b + 65536, 32768, sb + 32);
    }
    CP_WAIT(0);
    __syncthreads();   // ALL threads' Q copies visible

    uint32_t qf[2][4];
#pragma unroll
    for (int kc = 0; kc < 2; kc++) {
        int r = 16 * wid + arow;
        uint32_t off = (uint32_t)(r >> 6) * 4096 + swz64(r & 63, kc * 2 + achk);
        ldsm4(qf[kc], sb + OFF_Q2 + off);
    }

    float oacc[32][4];
#pragma unroll
    for (int j = 0; j < 32; j++)
#pragma unroll
        for (int c = 0; c < 4; c++) oacc[j][c] = 0.f;
    float lpart[2] = {0.f, 0.f};

    for (int i = 0; i < 64; i++) {
        MBARRIER_WAIT_PARITY(sb + (i & 1) * 8, (i >> 1) & 1);
        float sacc[8][4];
#pragma unroll
        for (int nf = 0; nf < 8; nf++)
#pragma unroll
            for (int c = 0; c < 4; c++) sacc[nf][c] = 0.f;
        const uint32_t Kb = sb + ((i & 1) ? OFF_K1 : OFF_K0);
#pragma unroll
        for (int kc = 0; kc < 2; kc++) {
#pragma unroll
            for (int j = 0; j < 4; j++) {
                uint32_t bK[4];
                ldsm4(bK, Kb + swz64(j * 16 + brow, kc * 2 + bchk));
                mma_fp(sacc[2 * j],     qf[kc], &bK[0]);
                mma_fp(sacc[2 * j + 1], qf[kc], &bK[2]);
            }
        }

        uint32_t pf[8][2];
#pragma unroll
        for (int nf = 0; nf < 8; nf++) {
            float p0 = exp2f(sacc[nf][0]);
            float p1 = exp2f(sacc[nf][1]);
            float p2 = exp2f(sacc[nf][2]);
            float p3 = exp2f(sacc[nf][3]);
            uint32_t hA = pack_bf16x2(p0, p1);
            uint32_t hB = pack_bf16x2(p2, p3);
            lpart[0] += __uint_as_float(hA << 16) + __uint_as_float(hA & 0xffff0000u);
            lpart[1] += __uint_as_float(hB << 16) + __uint_as_float(hB & 0xffff0000u);
            pf[nf][0] = hA;
            pf[nf][1] = hB;
        }

        const int vs = i % 3;
        MBARRIER_WAIT_PARITY(sb + 16 + vs * 8, (i / 3) & 1);
        const uint32_t Vb = sb + OFF_V0 + vs * 32768;
#pragma unroll
        for (int kk = 0; kk < 4; kk++) {
            uint32_t A[4] = {pf[2 * kk][0], pf[2 * kk][1], pf[2 * kk + 1][0], pf[2 * kk + 1][1]};
#pragma unroll
            for (int cj = 0; cj < 16; cj++) {
                uint32_t bV[4];
                ldsm4(bV, Vb + (cj * 16 + vrow) * 128 + ((kk * 32 + vcol) ^ vx));
                mma_bf(oacc[2 * cj],     A, &bV[0]);
                mma_bf(oacc[2 * cj + 1], A, &bV[2]);
            }
        }

        __syncthreads();
        if (t == 0) {
            if (i + 2 < 64) {
                MBARRIER_EXPECT_TX(sb + (i & 1) * 8, 4096);
                bulkcp(sb + ((i & 1) ? OFF_K1 : OFF_K0), kt_b + (size_t)(i + 2) * 4096, 4096, sb + (i & 1) * 8);
            }
            if (i + 3 < 64) {
                MBARRIER_EXPECT_TX(sb + 16 + vs * 8, 32768);
                bulkcp(sb + OFF_V0 + vs * 32768, vt_b + (size_t)(i + 3) * 32768, 32768, sb + 16 + vs * 8);
            }
        }
    }

    atomicAdd(&lsum_s[16 * wid + g],     lpart[0]);
    atomicAdd(&lsum_s[16 * wid + 8 + g], lpart[1]);
    __syncthreads();

    {
        const int rA = 16 * wid + g;
        const int rB = rA + 8;
        const float invA = 1.f / lsum_s[rA];
        const float invB = 1.f / lsum_s[rB];
        __half* hA = ao + (size_t)(b * N_ + m0 + rA) * C_;
        __half* hB = ao + (size_t)(b * N_ + m0 + rB) * C_;
#pragma unroll
        for (int cn = 0; cn < 32; cn++) {
            const int cb = cn * 8 + 2 * tg;
            *(uint32_t*)(hA + cb) = pack_h2(oacc[cn][0] * invA, oacc[cn][1] * invA);
            *(uint32_t*)(hB + cb) = pack_h2(oacc[cn][2] * invB, oacc[cn][3] * invB);
        }
    }
}

// ---------------------------------------------------------------------------
// Output projection: out = wo*AO + bo + x.  3-stage cp.async pipeline.
// ---------------------------------------------------------------------------
#define OP_WH 0
#define OP_WL 18432
#define OP_A  36864
#define OP_BUF 55296
#define OPROJ_SMEM 165888

__global__ __launch_bounds__(512, 1)
void oproj_mma_kernel(const __half* __restrict__ ao,
                      const __half* __restrict__ whi,
                      const __half* __restrict__ wlo,
                      const float* __restrict__ bo,
                      const float* __restrict__ x,
                      float* __restrict__ out)
{
    extern __shared__ char sm[];
    const uint32_t sb = smem_u32(sm);
    const int t = threadIdx.x;
    const int wid = t >> 5, lane = t & 31;
    const int g = lane >> 2, tg = lane & 3;
    const int oA = aoffA(lane), oB = aoffB(lane);
    const int wm = wid >> 2, wn = wid & 3;
    const int b = blockIdx.z, o0 = blockIdx.y * 128, m0 = blockIdx.x * 128;

    float oac[2][4][4];
#pragma unroll
    for (int i = 0; i < 2; i++)
#pragma unroll
        for (int j = 0; j < 4; j++)
#pragma unroll
            for (int c = 0; c < 4; c++) oac[i][j][c] = 0.f;

    auto load_stage = [&](int kt_, int buf) {
        const uint32_t base = sb + buf * OP_BUF;
#pragma unroll
        for (int it = 0; it < 6; it++) {
            int idx = t + it * 512;
            int arr = idx >> 10, rr = (idx >> 3) & 127, cc = idx & 7;
            uint32_t dst = base + arr * 18432 + rr * RS + cc * 16;
            const __half* src;
            if (arr == 0)      src = whi + (size_t)(o0 + rr) * C_ + kt_ + cc * 8;
            else if (arr == 1) src = wlo + (size_t)(o0 + rr) * C_ + kt_ + cc * 8;
            else               src = ao + (size_t)(b * N_ + m0 + rr) * C_ + kt_ + cc * 8;
            cpasync16(dst, src);
        }
        CP_COMMIT();
    };

    load_stage(0, 0);
    load_stage(64, 1);
    for (int s = 0; s < 4; s++) {
        if (s + 2 < 4) { load_stage((s + 2) * 64, (s + 2) % 3); CP_WAIT(2); }
        else if (s + 1 < 4) CP_WAIT(1);
        else CP_WAIT(0);
        __syncthreads();
        const uint32_t base = sb + (s % 3) * OP_BUF;
        const uint32_t Wh = base + OP_WH + (wm * 32) * RS + oA;
        const uint32_t Wl = base + OP_WL + (wm * 32) * RS + oA;
        const uint32_t Ap = base + OP_A  + (wn * 32) * RS + oB;
#pragma unroll
        for (int ks = 0; ks < 4; ks++) {
            uint32_t awh[2][4], awl[2][4];
#pragma unroll
            for (int mf = 0; mf < 2; mf++) {
                ldsm4(awh[mf], Wh + mf * 16 * RS + ks * 32);
                ldsm4(awl[mf], Wl + mf * 16 * RS + ks * 32);
            }
#pragma unroll
            for (int j = 0; j < 2; j++) {
                uint32_t bh[4];
                ldsm4(bh, Ap + j * 16 * RS + ks * 32);
#pragma unroll
                for (int h = 0; h < 2; h++) {
                    const int nf = 2 * j + h;
#pragma unroll
                    for (int mf = 0; mf < 2; mf++) {
                        mma_fp(oac[mf][nf], awh[mf], &bh[2 * h]);
                        mma_fp(oac[mf][nf], awl[mf], &bh[2 * h]);
                    }
                }
            }
        }
        __syncthreads();
    }

#pragma unroll
    for (int mf = 0; mf < 2; mf++) {
        const int rA = o0 + wm * 32 + mf * 16 + g;
        const int rB = rA + 8;
        const float bvA = bo[rA], bvB = bo[rB];
#pragma unroll
        for (int nf = 0; nf < 4; nf++) {
            const int m = m0 + wn * 32 + nf * 8 + 2 * tg;
            size_t iA = (size_t)(b * C_ + rA) * N_ + m;
            size_t iB = (size_t)(b * C_ + rB) * N_ + m;
            float2 xA = *(const float2*)&x[iA];
            float2 xB = *(const float2*)&x[iB];
            *(float2*)&out[iA] = make_float2(oac[mf][nf][0] + bvA + xA.x, oac[mf][nf][1] + bvA + xA.y);
            *(float2*)&out[iB] = make_float2(oac[mf][nf][2] + bvB + xB.x, oac[mf][nf][3] + bvB + xB.y);
        }
    }
}

// ---------------------------------------------------------------------------
extern "C" void kernel_launch(void* const* d_in, const int* in_sizes, int n_in,
                              void* d_out, int out_size)
{
    const float* x  = (const float*)d_in[0];
    const float* wq = (const float*)d_in[1];
    const float* bq = (const float*)d_in[2];
    const float* wk = (const float*)d_in[3];
    const float* bk = (const float*)d_in[4];
    const float* wv = (const float*)d_in[5];
    const float* bv = (const float*)d_in[6];
    const float* wo = (const float*)d_in[7];
    const float* bo = (const float*)d_in[8];
    float* out = (float*)d_out;

    char *gqt, *gkt, *gvt;
    __half *gao, *gxt, *gwoh, *gwol, *gwv, *gwq, *gwk;
    cudaGetSymbolAddress((void**)&gqt,  g_qt);
    cudaGetSymbolAddress((void**)&gkt,  g_kt);
    cudaGetSymbolAddress((void**)&gvt,  g_vt);
    cudaGetSymbolAddress((void**)&gao,  g_ao);
    cudaGetSymbolAddress((void**)&gxt,  g_xt);
    cudaGetSymbolAddress((void**)&gwoh, g_wohi);
    cudaGetSymbolAddress((void**)&gwol, g_wolo);
    cudaGetSymbolAddress((void**)&gwv,  g_wv);
    cudaGetSymbolAddress((void**)&gwq,  g_wq);
    cudaGetSymbolAddress((void**)&gwk,  g_wk);

    cudaFuncSetAttribute(attn_mma_kernel, cudaFuncAttributeMaxDynamicSharedMemorySize, ATTN_SMEM);
    cudaFuncSetAttribute(oproj_mma_kernel, cudaFuncAttributeMaxDynamicSharedMemorySize, OPROJ_SMEM);
    cudaFuncSetAttribute(v_mma_kernel, cudaFuncAttributeMaxDynamicSharedMemorySize, VP_SMEM);
    cudaFuncSetAttribute(qk_mma_kernel, cudaFuncAttributeMaxDynamicSharedMemorySize, QK_SMEM);

    wprep_all_kernel<<<dim3(C_ * C_ / 256, 4), 256>>>(wo, wv, wq, wk,
        gwoh, gwol, gwv, gwq, gwk);
    xt_pack_kernel<<<dim3(N_ / 64, C_ / 64, B_), 256>>>(x, gxt);
    qk_mma_kernel<<<dim3(N_ / 128, B_), 256, QK_SMEM>>>(
        gxt, gwq, gwk, bq, bk, gqt, gkt);
    v_mma_kernel<<<dim3(N_ / 128, C_ / 128, B_), 512, VP_SMEM>>>(
        gxt, gwv, bv, gvt);
    attn_mma_kernel<<<dim3(N_ / 128, B_), 256, ATTN_SMEM>>>(gqt, gkt, gvt, gao);
    oproj_mma_kernel<<<dim3(N_ / 128, C_ / 128, B_), 512, OPROJ_SMEM>>>(
        gao, gwoh, gwol, bo, x, out);
}

// round 17
// speedup vs baseline: 1.0258x; 1.0258x over previous
#include <cuda_runtime.h>
#include <cuda_bf16.h>
#include <cuda_fp16.h>
#include <math.h>
#include <stdint.h>

#define B_ 4
#define C_ 256
#define N_ 4096
#define D_ 32
#define LOG2E 1.4426950408889634f

// ---------------------------------------------------------------------------
// PTX helpers (base sm_100-safe)
// ---------------------------------------------------------------------------
__device__ __forceinline__ uint32_t smem_u32(const void* p) {
    uint32_t a;
    asm("{ .reg .u64 t; cvta.to.shared.u64 t, %1; cvt.u32.u64 %0, t; }" : "=r"(a) : "l"(p));
    return a;
}
#define MBARRIER_INIT(a, c) \
    asm volatile("mbarrier.init.shared.b64 [%0], %1;" :: "r"((uint32_t)(a)), "r"((uint32_t)(c)) : "memory")
#define MBARRIER_EXPECT_TX(a, n) \
    asm volatile("mbarrier.arrive.expect_tx.shared.b64 _, [%0], %1;" :: "r"((uint32_t)(a)), "r"((uint32_t)(n)) : "memory")
#define MBARRIER_WAIT_PARITY(a, ph) do { \
    uint32_t _m = (uint32_t)(a); uint32_t _p = (uint32_t)(ph); uint32_t _d; \
    asm volatile("{\n\t.reg .pred p;\n\tmbarrier.try_wait.parity.shared.b64 p, [%1], %2;\n\tselp.b32 %0,1,0,p;\n\t}" \
        : "=r"(_d) : "r"(_m), "r"(_p) : "memory"); \
    if (!_d) { \
        asm volatile("{\n\t.reg .pred P1;\n\tWL_%=:\n\tmbarrier.try_wait.parity.shared.b64 P1, [%0], %1;\n\t@P1 bra.uni WD_%=;\n\tbra.uni WL_%=;\n\tWD_%=:\n\t}" \
            :: "r"(_m), "r"(_p) : "memory"); \
    } } while (0)

__device__ __forceinline__ void cpasync16(uint32_t dst, const void* src) {
    asm volatile("cp.async.cg.shared.global [%0], [%1], 16;" :: "r"(dst), "l"(src) : "memory");
}
#define CP_COMMIT() asm volatile("cp.async.commit_group;" ::: "memory")
#define CP_WAIT(n)  asm volatile("cp.async.wait_group %0;" :: "n"(n) : "memory")

__device__ __forceinline__ void bulkcp(uint32_t dst, const void* src, uint32_t bytes, uint32_t mbar) {
    asm volatile("cp.async.bulk.shared::cta.global.mbarrier::complete_tx::bytes [%0], [%1], %2, [%3];"
                 :: "r"(dst), "l"(src), "r"(bytes), "r"(mbar) : "memory");
}

__device__ __forceinline__ void mma_bf(float* d, const uint32_t* a, const uint32_t* b) {
    asm volatile("mma.sync.aligned.m16n8k16.row.col.f32.bf16.bf16.f32 "
                 "{%0,%1,%2,%3}, {%4,%5,%6,%7}, {%8,%9}, {%0,%1,%2,%3};"
                 : "+f"(d[0]), "+f"(d[1]), "+f"(d[2]), "+f"(d[3])
                 : "r"(a[0]), "r"(a[1]), "r"(a[2]), "r"(a[3]), "r"(b[0]), "r"(b[1]));
}
__device__ __forceinline__ void mma_fp(float* d, const uint32_t* a, const uint32_t* b) {
    asm volatile("mma.sync.aligned.m16n8k16.row.col.f32.f16.f16.f32 "
                 "{%0,%1,%2,%3}, {%4,%5,%6,%7}, {%8,%9}, {%0,%1,%2,%3};"
                 : "+f"(d[0]), "+f"(d[1]), "+f"(d[2]), "+f"(d[3])
                 : "r"(a[0]), "r"(a[1]), "r"(a[2]), "r"(a[3]), "r"(b[0]), "r"(b[1]));
}
__device__ __forceinline__ void ldsm4(uint32_t* r, uint32_t addr) {
    asm volatile("ldmatrix.sync.aligned.m8n8.x4.shared.b16 {%0,%1,%2,%3}, [%4];"
                 : "=r"(r[0]), "=r"(r[1]), "=r"(r[2]), "=r"(r[3]) : "r"(addr));
}
__device__ __forceinline__ uint32_t pack_bf16x2(float x, float y) {
    __nv_bfloat162 h = __floats2bfloat162_rn(x, y);
    return *(uint32_t*)&h;
}
__device__ __forceinline__ uint32_t pack_h2(float x, float y) {
    __half2 h = __floats2half2_rn(x, y);
    return *(uint32_t*)&h;
}

#define RS 144
__device__ __forceinline__ int aoffA(int lane) { return (lane & 15) * RS + (lane >> 4) * 16; }
__device__ __forceinline__ int aoffB(int lane) { return ((lane & 7) + ((lane >> 4) << 3)) * RS + (lane & 8) * 2; }
__device__ __forceinline__ uint32_t swz64(int row, int chunk) {
    return (uint32_t)(row * 64 + ((chunk ^ ((row >> 1) & 3)) << 4));
}

// ---------------------------------------------------------------------------
// Scratch
// ---------------------------------------------------------------------------
__device__ char   g_qt [B_*64*64*64];
__device__ char   g_kt [B_*64*64*64];
__device__ char   g_vt [(size_t)B_*64*256*128];
__device__ __half g_ao [B_*N_*C_];
__device__ __half g_xt [B_*N_*C_];
__device__ __half g_wo [C_*C_];
__device__ __half g_wv [C_*C_];
__device__ __half g_wq [D_*C_];
__device__ __half g_wk [D_*C_];

// ---------------------------------------------------------------------------
// weight prep: all single fp16 (wq pre-scaled by log2e)
// ---------------------------------------------------------------------------
__global__ void wprep_all_kernel(const float* __restrict__ wo, const float* __restrict__ wv,
                                 const float* __restrict__ wq, const float* __restrict__ wk,
                                 __half* __restrict__ wop, __half* __restrict__ wvp,
                                 __half* __restrict__ wqp, __half* __restrict__ wkp)
{
    int which = blockIdx.y;
    int i = blockIdx.x * 256 + threadIdx.x;
    if (which == 0) {
        wop[i] = __float2half_rn(wo[i]);
    } else if (which == 1) {
        wvp[i] = __float2half_rn(wv[i]);
    } else if (which == 2) {
        if (i < D_ * C_) wqp[i] = __float2half_rn(wq[i] * LOG2E);
    } else {
        if (i < D_ * C_) wkp[i] = __float2half_rn(wk[i]);
    }
}

// ---------------------------------------------------------------------------
__global__ __launch_bounds__(256)
void xt_pack_kernel(const float* __restrict__ x, __half* __restrict__ xt)
{
    __shared__ float ts[64][65];
    const int b = blockIdx.z, c0 = blockIdx.y * 64, n0 = blockIdx.x * 64;
    const int t = threadIdx.x;
    const int rr = t >> 4, c4 = t & 15;

#pragma unroll
    for (int it = 0; it < 4; it++) {
        int row = it * 16 + rr;
        float4 v = *(const float4*)&x[(size_t)(b * C_ + c0 + row) * N_ + n0 + c4 * 4];
        ts[row][c4 * 4 + 0] = v.x; ts[row][c4 * 4 + 1] = v.y;
        ts[row][c4 * 4 + 2] = v.z; ts[row][c4 * 4 + 3] = v.w;
    }
    __syncthreads();
#pragma unroll
    for (int it = 0; it < 4; it++) {
        int n = it * 16 + rr;
        unsigned short hs[4];
#pragma unroll
        for (int e = 0; e < 4; e++)
            hs[e] = __half_as_ushort(__float2half_rn(ts[c4 * 4 + e][n]));
        *(uint2*)&xt[(size_t)(b * N_ + n0 + n) * C_ + c0 + c4 * 4] = *(uint2*)hs;
    }
}

// ---------------------------------------------------------------------------
// Q+K projection GEMM (fp16) -> 64B-row swizzled g_qt, g_kt
// ---------------------------------------------------------------------------
#define QK_XT 0
#define QK_WB 73728
#define QK_SMEM 110592

__global__ __launch_bounds__(256, 1)
void qk_mma_kernel(const __half* __restrict__ xt,
                   const __half* __restrict__ wqp, const __half* __restrict__ wkp,
                   const float* __restrict__ bq, const float* __restrict__ bk,
                   char* __restrict__ qt, char* __restrict__ kt)
{
    extern __shared__ char sm[];
    const uint32_t sb = smem_u32(sm);
    const int t = threadIdx.x;
    const int wid = t >> 5, lane = t & 31;
    const int g = lane >> 2, tg = lane & 3;
    const int oA = aoffA(lane), oB = aoffB(lane);
    const int wm = wid >> 1, wn = wid & 1;
    const int b = blockIdx.y, n0 = blockIdx.x * 128;

#pragma unroll
    for (int it = 0; it < 16; it++) {
        int idx = t + it * 256;
        int r = idx >> 5, cc = idx & 31;
        uint32_t off = (cc >> 3) * 18432 + r * RS + (cc & 7) * 16;
        cpasync16(sb + QK_XT + off, xt + (size_t)(b * N_ + n0 + r) * C_ + cc * 8);
    }
#pragma unroll
    for (int it = 0; it < 8; it++) {
        int idx = t + it * 256;
        int o = idx >> 5, cc = idx & 31;
        uint32_t off = (cc >> 3) * 9216 + o * RS + (cc & 7) * 16;
        const __half* sh = (o < 32) ? (wqp + (size_t)o * C_) : (wkp + (size_t)(o - 32) * C_);
        cpasync16(sb + QK_WB + off, sh + cc * 8);
    }
    CP_COMMIT();
    CP_WAIT(0);
    __syncthreads();

    float oac[2][4][4];
#pragma unroll
    for (int i = 0; i < 2; i++)
#pragma unroll
        for (int j = 0; j < 4; j++)
#pragma unroll
            for (int c = 0; c < 4; c++) oac[i][j][c] = 0.f;

#pragma unroll
    for (int kc = 0; kc < 4; kc++) {
#pragma unroll
        for (int ks = 0; ks < 4; ks++) {
            uint32_t ah[2][4];
#pragma unroll
            for (int mf = 0; mf < 2; mf++)
                ldsm4(ah[mf], sb + QK_XT + kc * 18432 + (wm * 32 + mf * 16) * RS + ks * 32 + oA);
#pragma unroll
            for (int j = 0; j < 2; j++) {
                uint32_t bh[4];
                ldsm4(bh, sb + QK_WB + kc * 9216 + (wn * 32 + j * 16) * RS + ks * 32 + oB);
#pragma unroll
                for (int h = 0; h < 2; h++)
#pragma unroll
                    for (int mf = 0; mf < 2; mf++)
                        mma_fp(oac[mf][j * 2 + h], ah[mf], &bh[2 * h]);
            }
        }
    }

#pragma unroll
    for (int mf = 0; mf < 2; mf++) {
#pragma unroll
        for (int half = 0; half < 2; half++) {
            const int rA = wm * 32 + mf * 16 + half * 8 + g;
            const int n = n0 + rA;
            const int tile = n >> 6, rr = n & 63;
#pragma unroll
            for (int hh = 0; hh < 4; hh++) {
                int o = wn * 32 + hh * 8 + 2 * tg;
                bool isq = (o < 32);
                int oo = isq ? o : (o - 32);
                float bb0 = isq ? bq[oo] * LOG2E : bk[oo];
                float bb1 = isq ? bq[oo + 1] * LOG2E : bk[oo + 1];
                float d0 = oac[mf][hh][half * 2 + 0] + bb0;
                float d1 = oac[mf][hh][half * 2 + 1] + bb1;
                char* dst = (isq ? qt : kt) + ((size_t)(b * 64 + tile) * 64) * 64;
                *(uint32_t*)(dst + swz64(rr, oo >> 3) + ((oo * 2) & 15)) = pack_h2(d0, d1);
            }
        }
    }
}

// ---------------------------------------------------------------------------
// V projection GEMM (fp16) -> swizzled bf16 g_vt.  3-stage cp.async pipeline.
// ---------------------------------------------------------------------------
#define VP_W 0
#define VP_X 18432
#define VP_BUF 36864
#define VP_SMEM 110592

__global__ __launch_bounds__(512, 1)
void v_mma_kernel(const __half* __restrict__ xt, const __half* __restrict__ wvp,
                  const float* __restrict__ bv, char* __restrict__ vt)
{
    extern __shared__ char sm[];
    const uint32_t sb = smem_u32(sm);
    const int t = threadIdx.x;
    const int wid = t >> 5, lane = t & 31;
    const int g = lane >> 2, tg = lane & 3;
    const int oA = aoffA(lane), oB = aoffB(lane);
    const int wm = wid >> 2, wn = wid & 3;
    const int b = blockIdx.z, o0 = blockIdx.y * 128, m0 = blockIdx.x * 128;

    float oac[2][4][4];
#pragma unroll
    for (int i = 0; i < 2; i++)
#pragma unroll
        for (int j = 0; j < 4; j++)
#pragma unroll
            for (int c = 0; c < 4; c++) oac[i][j][c] = 0.f;

    auto load_stage = [&](int kt_, int buf) {
        const uint32_t base = sb + buf * VP_BUF;
#pragma unroll
        for (int it = 0; it < 4; it++) {
            int idx = t + it * 512;
            int arr = idx >> 10, rr = (idx >> 3) & 127, cc = idx & 7;
            uint32_t dst = base + arr * 18432 + rr * RS + cc * 16;
            const __half* src = arr ? (xt + (size_t)(b * N_ + m0 + rr) * C_ + kt_ + cc * 8)
                                    : (wvp + (size_t)(o0 + rr) * C_ + kt_ + cc * 8);
            cpasync16(dst, src);
        }
        CP_COMMIT();
    };

    load_stage(0, 0);
    load_stage(64, 1);
    for (int s = 0; s < 4; s++) {
        if (s + 2 < 4) { load_stage((s + 2) * 64, (s + 2) % 3); CP_WAIT(2); }
        else if (s + 1 < 4) CP_WAIT(1);
        else CP_WAIT(0);
        __syncthreads();
        const uint32_t base = sb + (s % 3) * VP_BUF;
        const uint32_t Wp = base + VP_W + (wm * 32) * RS + oA;
        const uint32_t Xp = base + VP_X + (wn * 32) * RS + oB;
#pragma unroll
        for (int ks = 0; ks < 4; ks++) {
            uint32_t aw[2][4];
#pragma unroll
            for (int mf = 0; mf < 2; mf++)
                ldsm4(aw[mf], Wp + mf * 16 * RS + ks * 32);
#pragma unroll
            for (int j = 0; j < 2; j++) {
                uint32_t bh[4];
                ldsm4(bh, Xp + j * 16 * RS + ks * 32);
#pragma unroll
                for (int h = 0; h < 2; h++)
#pragma unroll
                    for (int mf = 0; mf < 2; mf++)
                        mma_fp(oac[mf][j * 2 + h], aw[mf], &bh[2 * h]);
            }
        }
        __syncthreads();
    }

#pragma unroll
    for (int mf = 0; mf < 2; mf++) {
#pragma unroll
        for (int half = 0; half < 2; half++) {
            const int rA = o0 + wm * 32 + mf * 16 + half * 8 + g;
            const float bvA = bv[rA];
            const int swx = (rA & 7) << 4;
#pragma unroll
            for (int nf = 0; nf < 4; nf++) {
                const int m = m0 + wn * 32 + nf * 8 + 2 * tg;
                const int tile = m >> 6, j = m & 63;
                char* dst = vt + ((size_t)(b * 64 + tile) * 256 + rA) * 128;
                *(uint32_t*)(dst + ((j * 2) ^ swx)) =
                    pack_bf16x2(oac[mf][nf][half * 2 + 0] + bvA, oac[mf][nf][half * 2 + 1] + bvA);
            }
        }
    }
}

// ---------------------------------------------------------------------------
// Flash attention, register-resident P (unchanged from R15).
// ---------------------------------------------------------------------------
#define OFF_LSUM 64
#define OFF_Q2   1024
#define OFF_K0   9216
#define OFF_K1   13312
#define OFF_V0   17408
#define ATTN_SMEM 115712

__global__ __launch_bounds__(256, 1)
void attn_mma_kernel(const char* __restrict__ qt,
                     const char* __restrict__ kt,
                     const char* __restrict__ vt,
                     __half* __restrict__ ao)
{
    extern __shared__ char sm[];
    const uint32_t sb = smem_u32(sm);
    const int t = threadIdx.x;
    const int wid = t >> 5, lane = t & 31;
    const int g = lane >> 2, tg = lane & 3;
    const int b = blockIdx.y, m0 = blockIdx.x * 128;

    const int arow = lane & 15, achk = lane >> 4;
    const int brow = (lane & 7) + ((lane >> 4) << 3), bchk = (lane >> 3) & 1;
    const int vrow = (lane & 7) + ((lane >> 4) << 3), vcol = (lane & 8) * 2, vx = (lane & 7) << 4;

    const char* qt_b = qt + ((size_t)(b * 64 + (m0 >> 6))) * 4096;
    const char* kt_b = kt + (size_t)b * 64 * 4096;
    const char* vt_b = vt + (size_t)b * 64 * 32768;

    float* lsum_s = (float*)(sm + OFF_LSUM);
    if (t == 0) {
        MBARRIER_INIT(sb + 0, 1);  MBARRIER_INIT(sb + 8, 1);
        MBARRIER_INIT(sb + 16, 1); MBARRIER_INIT(sb + 24, 1); MBARRIER_INIT(sb + 32, 1);
    }
    if (t < 128) lsum_s[t] = 0.f;

#pragma unroll
    for (int i = 0; i < 2; i++) {
        int idx = t + i * 256;
        cpasync16(sb + OFF_Q2 + idx * 16, qt_b + idx * 16);
    }
    CP_COMMIT();
    __syncthreads();

    if (t == 0) {
        MBARRIER_EXPECT_TX(sb + 0, 4096);  bulkcp(sb + OFF_K0, kt_b, 4096, sb + 0);
        MBARRIER_EXPECT_TX(sb + 8, 4096);  bulkcp(sb + OFF_K1, kt_b + 4096, 4096, sb + 8);
        MBARRIER_EXPECT_TX(sb + 16, 32768); bulkcp(sb + OFF_V0, vt_b, 32768, sb + 16);
        MBARRIER_EXPECT_TX(sb + 24, 32768); bulkcp(sb + OFF_V0 + 32768, vt_b + 32768, 32768, sb + 24);
        MBARRIER_EXPECT_TX(sb + 32, 32768); bulkcp(sb + OFF_V0 + 65536, vt_b + 65536, 32768, sb + 32);
    }
    CP_WAIT(0);
    __syncthreads();   // ALL threads' Q copies visible

    uint32_t qf[2][4];
#pragma unroll
    for (int kc = 0; kc < 2; kc++) {
        int r = 16 * wid + arow;
        uint32_t off = (uint32_t)(r >> 6) * 4096 + swz64(r & 63, kc * 2 + achk);
        ldsm4(qf[kc], sb + OFF_Q2 + off);
    }

    float oacc[32][4];
#pragma unroll
    for (int j = 0; j < 32; j++)
#pragma unroll
        for (int c = 0; c < 4; c++) oacc[j][c] = 0.f;
    float lpart[2] = {0.f, 0.f};

    for (int i = 0; i < 64; i++) {
        MBARRIER_WAIT_PARITY(sb + (i & 1) * 8, (i >> 1) & 1);
        float sacc[8][4];
#pragma unroll
        for (int nf = 0; nf < 8; nf++)
#pragma unroll
            for (int c = 0; c < 4; c++) sacc[nf][c] = 0.f;
        const uint32_t Kb = sb + ((i & 1) ? OFF_K1 : OFF_K0);
#pragma unroll
        for (int kc = 0; kc < 2; kc++) {
#pragma unroll
            for (int j = 0; j < 4; j++) {
                uint32_t bK[4];
                ldsm4(bK, Kb + swz64(j * 16 + brow, kc * 2 + bchk));
                mma_fp(sacc[2 * j],     qf[kc], &bK[0]);
                mma_fp(sacc[2 * j + 1], qf[kc], &bK[2]);
            }
        }

        uint32_t pf[8][2];
#pragma unroll
        for (int nf = 0; nf < 8; nf++) {
            float p0 = exp2f(sacc[nf][0]);
            float p1 = exp2f(sacc[nf][1]);
            float p2 = exp2f(sacc[nf][2]);
            float p3 = exp2f(sacc[nf][3]);
            uint32_t hA = pack_bf16x2(p0, p1);
            uint32_t hB = pack_bf16x2(p2, p3);
            lpart[0] += __uint_as_float(hA << 16) + __uint_as_float(hA & 0xffff0000u);
            lpart[1] += __uint_as_float(hB << 16) + __uint_as_float(hB & 0xffff0000u);
            pf[nf][0] = hA;
            pf[nf][1] = hB;
        }

        const int vs = i % 3;
        MBARRIER_WAIT_PARITY(sb + 16 + vs * 8, (i / 3) & 1);
        const uint32_t Vb = sb + OFF_V0 + vs * 32768;
#pragma unroll
        for (int kk = 0; kk < 4; kk++) {
            uint32_t A[4] = {pf[2 * kk][0], pf[2 * kk][1], pf[2 * kk + 1][0], pf[2 * kk + 1][1]};
#pragma unroll
            for (int cj = 0; cj < 16; cj++) {
                uint32_t bV[4];
                ldsm4(bV, Vb + (cj * 16 + vrow) * 128 + ((kk * 32 + vcol) ^ vx));
                mma_bf(oacc[2 * cj],     A, &bV[0]);
                mma_bf(oacc[2 * cj + 1], A, &bV[2]);
            }
        }

        __syncthreads();
        if (t == 0) {
            if (i + 2 < 64) {
                MBARRIER_EXPECT_TX(sb + (i & 1) * 8, 4096);
                bulkcp(sb + ((i & 1) ? OFF_K1 : OFF_K0), kt_b + (size_t)(i + 2) * 4096, 4096, sb + (i & 1) * 8);
            }
            if (i + 3 < 64) {
                MBARRIER_EXPECT_TX(sb + 16 + vs * 8, 32768);
                bulkcp(sb + OFF_V0 + vs * 32768, vt_b + (size_t)(i + 3) * 32768, 32768, sb + 16 + vs * 8);
            }
        }
    }

    atomicAdd(&lsum_s[16 * wid + g],     lpart[0]);
    atomicAdd(&lsum_s[16 * wid + 8 + g], lpart[1]);
    __syncthreads();

    {
        const int rA = 16 * wid + g;
        const int rB = rA + 8;
        const float invA = 1.f / lsum_s[rA];
        const float invB = 1.f / lsum_s[rB];
        __half* hA = ao + (size_t)(b * N_ + m0 + rA) * C_;
        __half* hB = ao + (size_t)(b * N_ + m0 + rB) * C_;
#pragma unroll
        for (int cn = 0; cn < 32; cn++) {
            const int cb = cn * 8 + 2 * tg;
            *(uint32_t*)(hA + cb) = pack_h2(oacc[cn][0] * invA, oacc[cn][1] * invA);
            *(uint32_t*)(hB + cb) = pack_h2(oacc[cn][2] * invB, oacc[cn][3] * invB);
        }
    }
}

// ---------------------------------------------------------------------------
// Output projection: out = wo*AO + bo + x.  SINGLE-term fp16, 3-stage pipeline.
// ---------------------------------------------------------------------------
#define OP_W  0
#define OP_A  18432
#define OP_BUF 36864
#define OPROJ_SMEM 110592

__global__ __launch_bounds__(512, 1)
void oproj_mma_kernel(const __half* __restrict__ ao,
                      const __half* __restrict__ wop,
                      const float* __restrict__ bo,
                      const float* __restrict__ x,
                      float* __restrict__ out)
{
    extern __shared__ char sm[];
    const uint32_t sb = smem_u32(sm);
    const int t = threadIdx.x;
    const int wid = t >> 5, lane = t & 31;
    const int g = lane >> 2, tg = lane & 3;
    const int oA = aoffA(lane), oB = aoffB(lane);
    const int wm = wid >> 2, wn = wid & 3;
    const int b = blockIdx.z, o0 = blockIdx.y * 128, m0 = blockIdx.x * 128;

    float oac[2][4][4];
#pragma unroll
    for (int i = 0; i < 2; i++)
#pragma unroll
        for (int j = 0; j < 4; j++)
#pragma unroll
            for (int c = 0; c < 4; c++) oac[i][j][c] = 0.f;

    auto load_stage = [&](int kt_, int buf) {
        const uint32_t base = sb + buf * OP_BUF;
#pragma unroll
        for (int it = 0; it < 4; it++) {
            int idx = t + it * 512;
            int arr = idx >> 10, rr = (idx >> 3) & 127, cc = idx & 7;
            uint32_t dst = base + arr * 18432 + rr * RS + cc * 16;
            const __half* src = arr ? (ao + (size_t)(b * N_ + m0 + rr) * C_ + kt_ + cc * 8)
                                    : (wop + (size_t)(o0 + rr) * C_ + kt_ + cc * 8);
            cpasync16(dst, src);
        }
        CP_COMMIT();
    };

    load_stage(0, 0);
    load_stage(64, 1);
    for (int s = 0; s < 4; s++) {
        if (s + 2 < 4) { load_stage((s + 2) * 64, (s + 2) % 3); CP_WAIT(2); }
        else if (s + 1 < 4) CP_WAIT(1);
        else CP_WAIT(0);
        __syncthreads();
        const uint32_t base = sb + (s % 3) * OP_BUF;
        const uint32_t Wp = base + OP_W + (wm * 32) * RS + oA;
        const uint32_t Ap = base + OP_A + (wn * 32) * RS + oB;
#pragma unroll
        for (int ks = 0; ks < 4; ks++) {
            uint32_t aw[2][4];
#pragma unroll
            for (int mf = 0; mf < 2; mf++)
                ldsm4(aw[mf], Wp + mf * 16 * RS + ks * 32);
#pragma unroll
            for (int j = 0; j < 2; j++) {
                uint32_t bh[4];
                ldsm4(bh, Ap + j * 16 * RS + ks * 32);
#pragma unroll
                for (int h = 0; h < 2; h++)
#pragma unroll
                    for (int mf = 0; mf < 2; mf++)
                        mma_fp(oac[mf][j * 2 + h], aw[mf], &bh[2 * h]);
            }
        }
        __syncthreads();
    }

#pragma unroll
    for (int mf = 0; mf < 2; mf++) {
        const int rA = o0 + wm * 32 + mf * 16 + g;
        const int rB = rA + 8;
        const float bvA = bo[rA], bvB = bo[rB];
#pragma unroll
        for (int nf = 0; nf < 4; nf++) {
            const int m = m0 + wn * 32 + nf * 8 + 2 * tg;
            size_t iA = (size_t)(b * C_ + rA) * N_ + m;
            size_t iB = (size_t)(b * C_ + rB) * N_ + m;
            float2 xA = *(const float2*)&x[iA];
            float2 xB = *(const float2*)&x[iB];
            *(float2*)&out[iA] = make_float2(oac[mf][nf][0] + bvA + xA.x, oac[mf][nf][1] + bvA + xA.y);
            *(float2*)&out[iB] = make_float2(oac[mf][nf][2] + bvB + xB.x, oac[mf][nf][3] + bvB + xB.y);
        }
    }
}

// ---------------------------------------------------------------------------
extern "C" void kernel_launch(void* const* d_in, const int* in_sizes, int n_in,
                              void* d_out, int out_size)
{
    const float* x  = (const float*)d_in[0];
    const float* wq = (const float*)d_in[1];
    const float* bq = (const float*)d_in[2];
    const float* wk = (const float*)d_in[3];
    const float* bk = (const float*)d_in[4];
    const float* wv = (const float*)d_in[5];
    const float* bv = (const float*)d_in[6];
    const float* wo = (const float*)d_in[7];
    const float* bo = (const float*)d_in[8];
    float* out = (float*)d_out;

    char *gqt, *gkt, *gvt;
    __half *gao, *gxt, *gwo, *gwv, *gwq, *gwk;
    cudaGetSymbolAddress((void**)&gqt, g_qt);
    cudaGetSymbolAddress((void**)&gkt, g_kt);
    cudaGetSymbolAddress((void**)&gvt, g_vt);
    cudaGetSymbolAddress((void**)&gao, g_ao);
    cudaGetSymbolAddress((void**)&gxt, g_xt);
    cudaGetSymbolAddress((void**)&gwo, g_wo);
    cudaGetSymbolAddress((void**)&gwv, g_wv);
    cudaGetSymbolAddress((void**)&gwq, g_wq);
    cudaGetSymbolAddress((void**)&gwk, g_wk);

    cudaFuncSetAttribute(attn_mma_kernel, cudaFuncAttributeMaxDynamicSharedMemorySize, ATTN_SMEM);
    cudaFuncSetAttribute(oproj_mma_kernel, cudaFuncAttributeMaxDynamicSharedMemorySize, OPROJ_SMEM);
    cudaFuncSetAttribute(v_mma_kernel, cudaFuncAttributeMaxDynamicSharedMemorySize, VP_SMEM);
    cudaFuncSetAttribute(qk_mma_kernel, cudaFuncAttributeMaxDynamicSharedMemorySize, QK_SMEM);

    wprep_all_kernel<<<dim3(C_ * C_ / 256, 4), 256>>>(wo, wv, wq, wk, gwo, gwv, gwq, gwk);
    xt_pack_kernel<<<dim3(N_ / 64, C_ / 64, B_), 256>>>(x, gxt);
    qk_mma_kernel<<<dim3(N_ / 128, B_), 256, QK_SMEM>>>(
        gxt, gwq, gwk, bq, bk, gqt, gkt);
    v_mma_kernel<<<dim3(N_ / 128, C_ / 128, B_), 512, VP_SMEM>>>(
        gxt, gwv, bv, gvt);
    attn_mma_kernel<<<dim3(N_ / 128, B_), 256, ATTN_SMEM>>>(gqt, gkt, gvt, gao);
    oproj_mma_kernel<<<dim3(N_ / 128, C_ / 128, B_), 512, OPROJ_SMEM>>>(
        gao, gwo, bo, x, out);
}